// round 1
// baseline (speedup 1.0000x reference)
#include <cuda_runtime.h>
#include <math_constants.h>

// TropicalConv2D: out[b,c,i,j] = max_{ki,kj} x_pad[b,c,i+ki-1, j+kj-1] + k[c,0,ki,kj]
// x: (8, 64, 224, 224) fp32, kernel: (64, 1, 3, 3) fp32, stride=1, pad=1, dil=1.
// Pure HBM-streaming stencil: 1 thread -> 4 outputs (float4), 3 row float4 loads + halo scalars.

#define XB 8
#define XC 64
#define XH 224
#define XW 224
#define W4 (XW / 4)   // 56 float4 groups per row

__global__ __launch_bounds__(256) void tropical_conv3x3_kernel(
    const float* __restrict__ x,
    const float* __restrict__ kern,
    float* __restrict__ out)
{
    const int total = XB * XC * XH * W4;
    int g = blockIdx.x * blockDim.x + threadIdx.x;
    if (g >= total) return;

    int j4    = g % W4;
    int t     = g / W4;
    int row   = t % XH;
    int plane = t / XH;          // b*C + c
    int c     = plane % XC;

    // 9 kernel taps for this channel (warp-uniform broadcast: planes span >> warp)
    const float* kc = kern + c * 9;
    float kr[3][3];
#pragma unroll
    for (int i = 0; i < 3; i++)
#pragma unroll
        for (int j = 0; j < 3; j++)
            kr[i][j] = __ldg(kc + i * 3 + j);

    const float* pp = x + (size_t)plane * (XH * XW);

    float a0 = -CUDART_INF_F, a1 = -CUDART_INF_F, a2 = -CUDART_INF_F, a3 = -CUDART_INF_F;

#pragma unroll
    for (int ki = 0; ki < 3; ki++) {
        int r = row - 1 + ki;
        if (r < 0 || r >= XH) continue;
        const float* rp = pp + r * XW + j4 * 4;
        float4 v = *reinterpret_cast<const float4*>(rp);
        float wl = (j4 > 0)      ? __ldg(rp - 1) : -CUDART_INF_F;
        float wr = (j4 < W4 - 1) ? __ldg(rp + 4) : -CUDART_INF_F;

        float k0 = kr[ki][0], k1 = kr[ki][1], k2 = kr[ki][2];
        // window: [wl, v.x, v.y, v.z, v.w, wr]
        a0 = fmaxf(a0, fmaxf(fmaxf(wl  + k0, v.x + k1), v.y + k2));
        a1 = fmaxf(a1, fmaxf(fmaxf(v.x + k0, v.y + k1), v.z + k2));
        a2 = fmaxf(a2, fmaxf(fmaxf(v.y + k0, v.z + k1), v.w + k2));
        a3 = fmaxf(a3, fmaxf(fmaxf(v.z + k0, v.w + k1), wr  + k2));
    }

    float4 o; o.x = a0; o.y = a1; o.z = a2; o.w = a3;
    *reinterpret_cast<float4*>(out + (size_t)g * 4) = o;
}

extern "C" void kernel_launch(void* const* d_in, const int* in_sizes, int n_in,
                              void* d_out, int out_size)
{
    const float* x = (const float*)d_in[0];
    const float* k = (const float*)d_in[1];
    float* out = (float*)d_out;

    const int total = XB * XC * XH * W4;    // 6,422,528 thread-groups
    const int threads = 256;
    const int blocks = (total + threads - 1) / threads;  // 25,088
    tropical_conv3x3_kernel<<<blocks, threads>>>(x, k, out);
}

// round 2
// speedup vs baseline: 1.0437x; 1.0437x over previous
#include <cuda_runtime.h>
#include <math_constants.h>

// TropicalConv2D (max-plus 3x3 depthwise), x:(8,64,224,224) f32, k:(64,1,3,3), s=1,p=1,d=1.
// R2: vertical register rolling (8 out rows/thread) + shuffle halos -> ~4x fewer L1 wavefronts.

#define XB 8
#define XC 64
#define XH 224
#define XW 224
#define W4 56          // float4 groups per row
#define RPT 8          // output rows per thread
#define BY 4           // row strips per block
#define ROWS_PER_BLOCK (RPT * BY)      // 32
#define BLOCKS_PER_PLANE (XH / ROWS_PER_BLOCK)  // 7

#define NEG_INF (-CUDART_INF_F)

struct Win { float wl, v0, v1, v2, v3, wr; };

__device__ __forceinline__ Win neg_win() {
    Win w; w.wl = w.v0 = w.v1 = w.v2 = w.v3 = w.wr = NEG_INF; return w;
}

__device__ __forceinline__ Win load_row(const float* __restrict__ pp, int r,
                                        int x_eff, int lane) {
    const float* rp = pp + r * XW + x_eff * 4;
    float4 v = *reinterpret_cast<const float4*>(rp);
    Win w;
    w.v0 = v.x; w.v1 = v.y; w.v2 = v.z; w.v3 = v.w;
    w.wl = __shfl_up_sync(0xffffffffu, v.w, 1);
    w.wr = __shfl_down_sync(0xffffffffu, v.x, 1);
    if (lane == 0)  w.wl = (x_eff > 0)      ? __ldg(rp - 1) : NEG_INF;
    if (lane == 31) w.wr = (x_eff < W4 - 1) ? __ldg(rp + 4) : NEG_INF;
    if (x_eff >= W4 - 1) w.wr = NEG_INF;   // true right edge (x=55 mid-warp)
    return w;
}

__device__ __forceinline__ void acc_row(const Win& w, float k0, float k1, float k2,
                                        float& a0, float& a1, float& a2, float& a3) {
    a0 = fmaxf(a0, fmaxf(fmaxf(w.wl + k0, w.v0 + k1), w.v1 + k2));
    a1 = fmaxf(a1, fmaxf(fmaxf(w.v0 + k0, w.v1 + k1), w.v2 + k2));
    a2 = fmaxf(a2, fmaxf(fmaxf(w.v1 + k0, w.v2 + k1), w.v3 + k2));
    a3 = fmaxf(a3, fmaxf(fmaxf(w.v2 + k0, w.v3 + k1), w.wr + k2));
}

__global__ __launch_bounds__(256) void tropical_conv3x3_roll(
    const float* __restrict__ x,
    const float* __restrict__ kern,
    float* __restrict__ out)
{
    const int plane = blockIdx.x / BLOCKS_PER_PLANE;       // b*C + c
    const int strip = blockIdx.x % BLOCKS_PER_PLANE;
    const int tx    = threadIdx.x;                          // 0..63
    const int lane  = tx & 31;
    const int x_eff = (tx < W4) ? tx : (W4 - 1);
    const bool active = (tx < W4);
    const int row0  = strip * ROWS_PER_BLOCK + threadIdx.y * RPT;

    const int c = plane & (XC - 1);
    const float* kc = kern + c * 9;
    float k00 = __ldg(kc + 0), k01 = __ldg(kc + 1), k02 = __ldg(kc + 2);
    float k10 = __ldg(kc + 3), k11 = __ldg(kc + 4), k12 = __ldg(kc + 5);
    float k20 = __ldg(kc + 6), k21 = __ldg(kc + 7), k22 = __ldg(kc + 8);

    const float* pp = x   + (size_t)plane * (XH * XW);
    float*       op = out + (size_t)plane * (XH * XW);

    // rolling windows: wm = input row i-1, wc = row i, wp = row i+1
    Win wm = (row0 > 0) ? load_row(pp, row0 - 1, x_eff, lane) : neg_win();
    Win wc = load_row(pp, row0, x_eff, lane);
    Win wp;

#pragma unroll
    for (int i = 0; i < RPT; i++) {
        const int r = row0 + i;
        wp = (r + 1 < XH) ? load_row(pp, r + 1, x_eff, lane) : neg_win();

        float a0 = NEG_INF, a1 = NEG_INF, a2 = NEG_INF, a3 = NEG_INF;
        acc_row(wm, k00, k01, k02, a0, a1, a2, a3);
        acc_row(wc, k10, k11, k12, a0, a1, a2, a3);
        acc_row(wp, k20, k21, k22, a0, a1, a2, a3);

        if (active) {
            float4 o; o.x = a0; o.y = a1; o.z = a2; o.w = a3;
            *reinterpret_cast<float4*>(op + r * XW + x_eff * 4) = o;
        }
        wm = wc; wc = wp;
    }
}

extern "C" void kernel_launch(void* const* d_in, const int* in_sizes, int n_in,
                              void* d_out, int out_size)
{
    const float* x = (const float*)d_in[0];
    const float* k = (const float*)d_in[1];
    float* out = (float*)d_out;

    dim3 block(64, BY, 1);                                  // 256 threads
    dim3 grid(XB * XC * BLOCKS_PER_PLANE, 1, 1);            // 512 * 7 = 3584 blocks
    tropical_conv3x3_roll<<<grid, block>>>(x, k, out);
}

// round 3
// speedup vs baseline: 1.2516x; 1.1992x over previous
#include <cuda_runtime.h>
#include <math_constants.h>

// TropicalConv2D (max-plus 3x3 depthwise), x:(8,64,224,224) f32, k:(64,1,3,3), s=1,p=1,d=1.
// R3: software-pipelined register rolling (prefetch row r+2 raw), seam scalars in load stage,
//     streaming output stores (__stwt) to keep x resident in the 126MB L2.

#define XB 8
#define XC 64
#define XH 224
#define XW 224
#define W4 56          // float4 groups per row
#define RPT 8          // output rows per thread
#define BY 4           // row strips per block
#define ROWS_PER_BLOCK (RPT * BY)               // 32
#define BLOCKS_PER_PLANE (XH / ROWS_PER_BLOCK)  // 7

#define NEG_INF (-CUDART_INF_F)

// Raw per-row data: vector + (edge-lane-only) seam scalars. All loaded in the load stage.
struct Raw { float v0, v1, v2, v3, l, r; };
// Shuffle-resolved 6-wide window.
struct Win { float wl, v0, v1, v2, v3, wr; };

__device__ __forceinline__ Raw neg_raw() {
    Raw w; w.v0 = w.v1 = w.v2 = w.v3 = w.l = w.r = NEG_INF; return w;
}

// Load stage: LDG.128 + predicated seam scalars. No shuffles here.
__device__ __forceinline__ Raw load_raw(const float* __restrict__ pp, int r,
                                        int x_eff, int lane) {
    Raw w;
    if (r < 0 || r >= XH) return neg_raw();
    const float* rp = pp + r * XW + x_eff * 4;
    float4 v = *reinterpret_cast<const float4*>(rp);
    w.v0 = v.x; w.v1 = v.y; w.v2 = v.z; w.v3 = v.w;
    w.l = NEG_INF; w.r = NEG_INF;
    if (lane == 0  && x_eff > 0)      w.l = __ldg(rp - 1);
    if (lane == 31 && x_eff < W4 - 1) w.r = __ldg(rp + 4);
    return w;
}

// Window stage: pure SHFL + select (runs one iteration after the load was issued).
__device__ __forceinline__ Win make_win(const Raw& w, int x_eff, int lane) {
    Win o;
    o.v0 = w.v0; o.v1 = w.v1; o.v2 = w.v2; o.v3 = w.v3;
    o.wl = __shfl_up_sync(0xffffffffu, w.v3, 1);
    o.wr = __shfl_down_sync(0xffffffffu, w.v0, 1);
    if (lane == 0)       o.wl = w.l;
    if (lane == 31)      o.wr = w.r;
    if (x_eff >= W4 - 1) o.wr = NEG_INF;   // true right image edge
    return o;
}

__device__ __forceinline__ void acc_row(const Win& w, float k0, float k1, float k2,
                                        float& a0, float& a1, float& a2, float& a3) {
    a0 = fmaxf(a0, fmaxf(fmaxf(w.wl + k0, w.v0 + k1), w.v1 + k2));
    a1 = fmaxf(a1, fmaxf(fmaxf(w.v0 + k0, w.v1 + k1), w.v2 + k2));
    a2 = fmaxf(a2, fmaxf(fmaxf(w.v1 + k0, w.v2 + k1), w.v3 + k2));
    a3 = fmaxf(a3, fmaxf(fmaxf(w.v2 + k0, w.v3 + k1), w.wr + k2));
}

__global__ __launch_bounds__(256, 5) void tropical_conv3x3_pipe(
    const float* __restrict__ x,
    const float* __restrict__ kern,
    float* __restrict__ out)
{
    const int plane = blockIdx.x / BLOCKS_PER_PLANE;       // b*C + c
    const int strip = blockIdx.x % BLOCKS_PER_PLANE;
    const int tx    = threadIdx.x;                          // 0..63
    const int lane  = tx & 31;
    const int x_eff = (tx < W4) ? tx : (W4 - 1);
    const bool active = (tx < W4);
    const int row0  = strip * ROWS_PER_BLOCK + threadIdx.y * RPT;

    const int c = plane & (XC - 1);
    const float* kc = kern + c * 9;
    const float k00 = __ldg(kc + 0), k01 = __ldg(kc + 1), k02 = __ldg(kc + 2);
    const float k10 = __ldg(kc + 3), k11 = __ldg(kc + 4), k12 = __ldg(kc + 5);
    const float k20 = __ldg(kc + 6), k21 = __ldg(kc + 7), k22 = __ldg(kc + 8);

    const float* pp = x   + (size_t)plane * (XH * XW);
    float*       op = out + (size_t)plane * (XH * XW);

    // Prologue: issue three independent loads back-to-back (MLP>=3), then resolve windows.
    Raw rm = load_raw(pp, row0 - 1, x_eff, lane);
    Raw rc = load_raw(pp, row0,     x_eff, lane);
    Raw rp = load_raw(pp, row0 + 1, x_eff, lane);
    Win wm = make_win(rm, x_eff, lane);
    Win wc = make_win(rc, x_eff, lane);

#pragma unroll
    for (int i = 0; i < RPT; i++) {
        const int r = row0 + i;
        // Prefetch row r+2 FIRST: its latency is covered by this iteration's
        // shuffles + 72 FP ops + store.
        Raw rn = load_raw(pp, r + 2, x_eff, lane);

        // Resolve the window for row r+1 (raw data loaded last iteration).
        Win wp = make_win(rp, x_eff, lane);

        float a0 = NEG_INF, a1 = NEG_INF, a2 = NEG_INF, a3 = NEG_INF;
        acc_row(wm, k00, k01, k02, a0, a1, a2, a3);
        acc_row(wc, k10, k11, k12, a0, a1, a2, a3);
        acc_row(wp, k20, k21, k22, a0, a1, a2, a3);

        if (active) {
            float4 o; o.x = a0; o.y = a1; o.z = a2; o.w = a3;
            // Streaming store: out is never re-read; evict-first keeps x in L2.
            __stwt(reinterpret_cast<float4*>(op + r * XW + x_eff * 4), o);
        }
        wm = wc; wc = wp; rp = rn;
    }
}

extern "C" void kernel_launch(void* const* d_in, const int* in_sizes, int n_in,
                              void* d_out, int out_size)
{
    const float* x = (const float*)d_in[0];
    const float* k = (const float*)d_in[1];
    float* out = (float*)d_out;

    dim3 block(64, BY, 1);                                  // 256 threads
    dim3 grid(XB * XC * BLOCKS_PER_PLANE, 1, 1);            // 512 * 7 = 3584 blocks
    tropical_conv3x3_pipe<<<grid, block>>>(x, k, out);
}

// round 4
// speedup vs baseline: 1.2526x; 1.0008x over previous
#include <cuda_runtime.h>
#include <math_constants.h>

// TropicalConv2D (max-plus 3x3 depthwise), x:(8,64,224,224) f32, k:(64,1,3,3), s=1,p=1,d=1.
// R4: one full row per warp (28 lanes x 8 floats). No seam scalar loads (halos = image
//     edges = -inf). Software pipelined, streaming stores.

#define XB 8
#define XC 64
#define XH 224
#define XW 224
#define LANES 28          // active lanes per warp (28*8 = 224 = full row)
#define RPT 8             // output rows per warp
#define WY 7              // warps per block
#define ROWS_PER_BLOCK (RPT * WY)               // 56
#define BLOCKS_PER_PLANE (XH / ROWS_PER_BLOCK)  // 4

#define NEG_INF (-CUDART_INF_F)

struct Raw { float v[8]; };          // 8 contiguous input floats (2 x float4)
struct Win { float w[10]; };         // wl + 8 + wr

__device__ __forceinline__ Raw neg_raw() {
    Raw r;
#pragma unroll
    for (int i = 0; i < 8; i++) r.v[i] = NEG_INF;
    return r;
}

// Load stage: 2 independent LDG.128, no shuffles, no scalar seams.
__device__ __forceinline__ Raw load_raw(const float* __restrict__ rowbase, int r) {
    if (r < 0 || r >= XH) return neg_raw();
    const float* rp = rowbase + r * XW;
    float4 a = *reinterpret_cast<const float4*>(rp);
    float4 b = *reinterpret_cast<const float4*>(rp + 4);
    Raw w;
    w.v[0] = a.x; w.v[1] = a.y; w.v[2] = a.z; w.v[3] = a.w;
    w.v[4] = b.x; w.v[5] = b.y; w.v[6] = b.z; w.v[7] = b.w;
    return w;
}

// Window stage: 2 shuffles + edge overrides. Halos are true image edges (-inf).
__device__ __forceinline__ Win make_win(const Raw& r, int lane) {
    Win o;
#pragma unroll
    for (int i = 0; i < 8; i++) o.w[i + 1] = r.v[i];
    float wl = __shfl_up_sync(0xffffffffu,   r.v[7], 1);
    float wr = __shfl_down_sync(0xffffffffu, r.v[0], 1);
    o.w[0] = (lane == 0) ? NEG_INF : wl;
    o.w[9] = (lane >= LANES - 1) ? NEG_INF : wr;
    return o;
}

// First window row: writes accumulators directly (no -inf init).
__device__ __forceinline__ void acc_first(const Win& w, float k0, float k1, float k2,
                                          float* a) {
#pragma unroll
    for (int j = 0; j < 8; j++)
        a[j] = fmaxf(fmaxf(w.w[j] + k0, w.w[j + 1] + k1), w.w[j + 2] + k2);
}

__device__ __forceinline__ void acc_row(const Win& w, float k0, float k1, float k2,
                                        float* a) {
#pragma unroll
    for (int j = 0; j < 8; j++)
        a[j] = fmaxf(a[j], fmaxf(fmaxf(w.w[j] + k0, w.w[j + 1] + k1), w.w[j + 2] + k2));
}

__global__ __launch_bounds__(224) void tropical_conv3x3_wide(
    const float* __restrict__ x,
    const float* __restrict__ kern,
    float* __restrict__ out)
{
    const int plane = blockIdx.x >> 2;                 // b*C + c  (4 strips/plane)
    const int strip = blockIdx.x & 3;
    const int lane  = threadIdx.x;                     // 0..31
    const int xl    = (lane < LANES) ? lane : (LANES - 1);   // clamp dup lanes
    const bool active = (lane < LANES);
    const int row0  = strip * ROWS_PER_BLOCK + threadIdx.y * RPT;

    const int c = plane & (XC - 1);
    const float* kc = kern + c * 9;
    const float k00 = __ldg(kc + 0), k01 = __ldg(kc + 1), k02 = __ldg(kc + 2);
    const float k10 = __ldg(kc + 3), k11 = __ldg(kc + 4), k12 = __ldg(kc + 5);
    const float k20 = __ldg(kc + 6), k21 = __ldg(kc + 7), k22 = __ldg(kc + 8);

    const float* rowbase = x + (size_t)plane * (XH * XW) + xl * 8;
    float*       orow    = out + (size_t)plane * (XH * XW) + xl * 8;

    // Prologue: 3 independent row loads in flight, then resolve first two windows.
    Raw rm = load_raw(rowbase, row0 - 1);
    Raw rc = load_raw(rowbase, row0);
    Raw rp = load_raw(rowbase, row0 + 1);
    Win wm = make_win(rm, lane);
    Win wc = make_win(rc, lane);

#pragma unroll
    for (int i = 0; i < RPT; i++) {
        const int r = row0 + i;
        // Prefetch row r+2 raw first; latency covered by this iteration's compute+store.
        Raw rn = load_raw(rowbase, r + 2);
        // Resolve window for row r+1 (loaded last iteration).
        Win wp = make_win(rp, lane);

        float a[8];
        acc_first(wm, k00, k01, k02, a);
        acc_row(wc, k10, k11, k12, a);
        acc_row(wp, k20, k21, k22, a);

        if (active) {
            float4 o0; o0.x = a[0]; o0.y = a[1]; o0.z = a[2]; o0.w = a[3];
            float4 o1; o1.x = a[4]; o1.y = a[5]; o1.z = a[6]; o1.w = a[7];
            float* dst = orow + r * XW;
            __stwt(reinterpret_cast<float4*>(dst),     o0);
            __stwt(reinterpret_cast<float4*>(dst + 4), o1);
        }
        wm = wc; wc = wp; rp = rn;
    }
}

extern "C" void kernel_launch(void* const* d_in, const int* in_sizes, int n_in,
                              void* d_out, int out_size)
{
    const float* x = (const float*)d_in[0];
    const float* k = (const float*)d_in[1];
    float* out = (float*)d_out;

    dim3 block(32, WY, 1);                               // 224 threads
    dim3 grid(XB * XC * BLOCKS_PER_PLANE, 1, 1);         // 512 * 4 = 2048 blocks
    tropical_conv3x3_wide<<<grid, block>>>(x, k, out);
}